// round 1
// baseline (speedup 1.0000x reference)
#include <cuda_runtime.h>
#include <cuda_bf16.h>
#include <cstddef>

// Problem constants
#define PB 64      // batches
#define PK 64      // classes
#define PN 16      // shots per class
#define PM 512     // test points per batch
#define PD 512     // feature dim
#define COLS (PK * PN)   // 1024 train rows per batch ("columns" of the GEMM)

// GEMM tiling
#define BM 64
#define BN 64
#define BK 16
#define TM 4
#define TN 4

// Scratch for precomputed squared norms (allocation-free: __device__ globals)
__device__ float g_trsq[PB * COLS];   // ||train[b,k,n]||^2  -> [b, k*16+n]
__device__ float g_tesq[PB * PM];     // ||test[b,m]||^2     -> [b, m]

// ---------------------------------------------------------------------------
// Kernel 1: per-row sum of squares (rows of length 512). One warp per row.
// mode 0 -> train (rows = PB*COLS), mode 1 -> test (rows = PB*PM)
// ---------------------------------------------------------------------------
__global__ void sumsq_kernel(const float* __restrict__ x, int rows, int mode)
{
    int gwarp = (blockIdx.x * blockDim.x + threadIdx.x) >> 5;
    int lane  = threadIdx.x & 31;
    if (gwarp >= rows) return;

    const float4* p = reinterpret_cast<const float4*>(x + (size_t)gwarp * PD);
    float s = 0.f;
#pragma unroll
    for (int i = 0; i < PD / 4 / 32; ++i) {        // 4 float4 per lane
        float4 v = p[lane + i * 32];
        s += v.x * v.x + v.y * v.y + v.z * v.z + v.w * v.w;
    }
#pragma unroll
    for (int o = 16; o; o >>= 1) s += __shfl_xor_sync(0xffffffffu, s, o);

    if (lane == 0) {
        if (mode == 0) g_trsq[gwarp] = s;
        else           g_tesq[gwarp] = s;
    }
}

// ---------------------------------------------------------------------------
// Kernel 2: fused batched GEMM (test . train^T) + score epilogue + max over n.
// Block computes a 64(m) x 64(kn) tile for one batch; the 64 kn-columns are
// exactly 4 classes (16 shots each), so max-over-n stays inside the block.
// ---------------------------------------------------------------------------
__global__ __launch_bounds__(256, 4)
void nearest_kernel(const float* __restrict__ train,
                    const float* __restrict__ test,
                    float* __restrict__ out)
{
    __shared__ float smem[BM * BN];            // 16 KB; GEMM tiles then scores
    float* As = smem;                          // [BK][BM]
    float* Bs = smem + BK * BM;                // [BK][BN]

    const int b  = blockIdx.z;
    const int m0 = blockIdx.y * BM;
    const int c0 = blockIdx.x * BN;            // first kn column
    const int tid = threadIdx.x;
    const int tx = tid & 15;                   // 0..15 -> column group
    const int ty = tid >> 4;                   // 0..15 -> row group

    const float* A  = test  + (size_t)b * PM   * PD;   // [512][512]
    const float* Bm = train + (size_t)b * COLS * PD;   // [1024][512]

    // cooperative load indices: one float4 per thread per tile
    const int lr  = tid >> 2;                  // 0..63  (tile row)
    const int lc4 = tid & 3;                   // 0..3   (which float4 along D)

    const float* aptr = A  + (size_t)(m0 + lr) * PD + lc4 * 4;
    const float* bptr = Bm + (size_t)(c0 + lr) * PD + lc4 * 4;

    float acc[TM][TN];
#pragma unroll
    for (int i = 0; i < TM; ++i)
#pragma unroll
        for (int j = 0; j < TN; ++j) acc[i][j] = 0.f;

    for (int d0 = 0; d0 < PD; d0 += BK) {
        float4 av = *reinterpret_cast<const float4*>(aptr + d0);
        float4 bv = *reinterpret_cast<const float4*>(bptr + d0);

        __syncthreads();   // previous iteration's reads done before overwrite
        // transposed store: smem tile [BK][64]
        As[(lc4 * 4 + 0) * BM + lr] = av.x;
        As[(lc4 * 4 + 1) * BM + lr] = av.y;
        As[(lc4 * 4 + 2) * BM + lr] = av.z;
        As[(lc4 * 4 + 3) * BM + lr] = av.w;
        Bs[(lc4 * 4 + 0) * BN + lr] = bv.x;
        Bs[(lc4 * 4 + 1) * BN + lr] = bv.y;
        Bs[(lc4 * 4 + 2) * BN + lr] = bv.z;
        Bs[(lc4 * 4 + 3) * BN + lr] = bv.w;
        __syncthreads();

#pragma unroll
        for (int kk = 0; kk < BK; ++kk) {
            float4 ra = *reinterpret_cast<const float4*>(&As[kk * BM + ty * 4]);
            float4 rb = *reinterpret_cast<const float4*>(&Bs[kk * BN + tx * 4]);
            float a4[4] = {ra.x, ra.y, ra.z, ra.w};
            float b4[4] = {rb.x, rb.y, rb.z, rb.w};
#pragma unroll
            for (int i = 0; i < TM; ++i)
#pragma unroll
                for (int j = 0; j < TN; ++j)
                    acc[i][j] = fmaf(a4[i], b4[j], acc[i][j]);
        }
    }

    // ---- epilogue: scores into smem, then max over shots (n) --------------
    __syncthreads();       // mainloop smem reads finished

    float trq[TN], teq[TM];
#pragma unroll
    for (int j = 0; j < TN; ++j) trq[j] = g_trsq[b * COLS + c0 + tx * 4 + j];
#pragma unroll
    for (int i = 0; i < TM; ++i) teq[i] = g_tesq[b * PM + m0 + ty * 4 + i];

    float* SC = smem;      // [64][64] scores
#pragma unroll
    for (int i = 0; i < TM; ++i)
#pragma unroll
        for (int j = 0; j < TN; ++j)
            SC[(ty * 4 + i) * BN + tx * 4 + j] =
                2.f * acc[i][j] - trq[j] - teq[i];
    __syncthreads();

    // 256 threads -> 64 rows x 4 classes; each reduces 16 shot-scores
    const int m  = tid >> 2;       // 0..63
    const int kl = tid & 3;        // 0..3
    const float* row = SC + m * BN + kl * PN;
    float mx = row[0];
#pragma unroll
    for (int n = 1; n < PN; ++n) mx = fmaxf(mx, row[n]);

    const int kGlobal = blockIdx.x * (BN / PN) + kl;
    out[(size_t)b * PM * PK + (size_t)(m0 + m) * PK + kGlobal] = mx;
}

// ---------------------------------------------------------------------------
extern "C" void kernel_launch(void* const* d_in, const int* in_sizes, int n_in,
                              void* d_out, int out_size)
{
    // Identify inputs by size (defensive against metadata ordering):
    // train = 64*64*16*512 = 33,554,432 elems; test = 64*512*512 = 16,777,216.
    const float* train = (const float*)d_in[0];
    const float* test  = (const float*)d_in[1];
    if (in_sizes[0] == PB * PM * PD && in_sizes[1] == PB * PK * PN * PD) {
        train = (const float*)d_in[1];
        test  = (const float*)d_in[0];
    }
    float* out = (float*)d_out;

    // 1) squared norms (one warp per row, 8 warps per block)
    {
        int rowsT = PB * COLS;                 // 65536
        int rowsE = PB * PM;                   // 32768
        sumsq_kernel<<<rowsT / 8, 256>>>(train, rowsT, 0);
        sumsq_kernel<<<rowsE / 8, 256>>>(test,  rowsE, 1);
    }

    // 2) fused GEMM + epilogue
    dim3 grid(COLS / BN, PM / BM, PB);         // (16, 8, 64)
    nearest_kernel<<<grid, 256>>>(train, test, out);
}

// round 6
// speedup vs baseline: 3.2228x; 3.2228x over previous
#include <cuda_runtime.h>
#include <cstdint>
#include <cstddef>

// ---------------- problem constants ----------------
#define PB 64
#define PK 64
#define PN 16
#define PM 512
#define PD 512
#define COLS (PK * PN)        // 1024 train rows per batch

// ---------------- GEMM tiling ----------------
#define BM 128                // test rows per CTA
#define BN 128                // train rows per CTA
#define BK 16                 // K per chunk
#define CHUNKS (PD / BK)      // 32
#define NTHREADS 256
#define STR 20                // smem row stride in elements (padding: conflict-free)

// scratch (allocation-free)
__device__ float g_trsq[PB * COLS];
__device__ float g_tesq[PB * PM];

__device__ __forceinline__ uint32_t f2tf32(float f) {
    uint32_t u;
    asm("cvt.rna.tf32.f32 %0, %1;" : "=r"(u) : "f"(f));
    return u;
}
__device__ __forceinline__ void mma_tf32(float* c, const uint32_t* a, const uint32_t* b) {
    asm volatile(
        "mma.sync.aligned.m16n8k8.row.col.f32.tf32.tf32.f32 "
        "{%0,%1,%2,%3}, {%4,%5,%6,%7}, {%8,%9}, {%0,%1,%2,%3};"
        : "+f"(c[0]), "+f"(c[1]), "+f"(c[2]), "+f"(c[3])
        : "r"(a[0]), "r"(a[1]), "r"(a[2]), "r"(a[3]), "r"(b[0]), "r"(b[1]));
}

// ---------------------------------------------------------------------------
// Kernel 1: exact fp32 squared norms (one warp per row of 512)
// ---------------------------------------------------------------------------
__global__ void sumsq_kernel(const float* __restrict__ x, int rows, int mode)
{
    int gwarp = (blockIdx.x * blockDim.x + threadIdx.x) >> 5;
    int lane  = threadIdx.x & 31;
    if (gwarp >= rows) return;
    const float4* p = reinterpret_cast<const float4*>(x + (size_t)gwarp * PD);
    float s = 0.f;
#pragma unroll
    for (int i = 0; i < PD / 128; ++i) {
        float4 v = p[lane + i * 32];
        s += v.x * v.x + v.y * v.y + v.z * v.z + v.w * v.w;
    }
#pragma unroll
    for (int o = 16; o; o >>= 1) s += __shfl_xor_sync(0xffffffffu, s, o);
    if (lane == 0) { if (mode == 0) g_trsq[gwarp] = s; else g_tesq[gwarp] = s; }
}

// ---------------------------------------------------------------------------
// Kernel 2: tf32 mma.sync GEMM, register-staged double buffer (NO cp.async),
// static smem only, fused register-resident epilogue (max over 16-shot classes)
// CTA: 128(m) x 128(n) x 512(k); 8 warps (2m x 4n), warp tile 64x32
// ---------------------------------------------------------------------------
__global__ __launch_bounds__(NTHREADS)
void nearest_mma(const float* __restrict__ train, const float* __restrict__ test,
                 float* __restrict__ out)
{
    __shared__ uint32_t sA[2][BM * STR];
    __shared__ uint32_t sB[2][BN * STR];
    __shared__ float trs[BN], tes[BM];

    const int tid  = threadIdx.x;
    const int wid  = tid >> 5;
    const int lane = tid & 31;
    const int g = lane >> 2;              // 0..7
    const int t = lane & 3;               // 0..3
    const int wm = (wid & 1) * 64;        // warp m offset
    const int wn = (wid >> 1) * 32;       // warp n offset (= 2 classes)

    const int b  = blockIdx.z;
    const int m0 = blockIdx.y * BM;
    const int c0 = blockIdx.x * BN;

    const float* test_b  = test  + ((size_t)b * PM   + m0) * PD;
    const float* train_b = train + ((size_t)b * COLS + c0) * PD;

    // per-thread staging coordinates: 512 float4 per operand tile / 256 threads
    const int row0 = tid >> 2;                 // 0..63
    const int cq   = tid & 3;                  // float4 slot within 16 floats
    const float4* gA0 = reinterpret_cast<const float4*>(test_b  + (size_t)row0        * PD) + cq;
    const float4* gA1 = reinterpret_cast<const float4*>(test_b  + (size_t)(row0 + 64) * PD) + cq;
    const float4* gB0 = reinterpret_cast<const float4*>(train_b + (size_t)row0        * PD) + cq;
    const float4* gB1 = reinterpret_cast<const float4*>(train_b + (size_t)(row0 + 64) * PD) + cq;

    float acc[4][4][4];
#pragma unroll
    for (int i = 0; i < 4; ++i)
#pragma unroll
        for (int j = 0; j < 4; ++j)
#pragma unroll
            for (int r = 0; r < 4; ++r) acc[i][j][r] = 0.f;

    float4 ra0, ra1, rb0, rb1;
    // load chunk 0
    ra0 = gA0[0]; ra1 = gA1[0]; rb0 = gB0[0]; rb1 = gB1[0];

    // store helper (tf32-convert at store time)
    auto store_stage = [&](int s, const float4& a0, const float4& a1,
                           const float4& b0, const float4& b1) {
        uint32_t* pa0 = &sA[s][row0 * STR + cq * 4];
        uint32_t* pa1 = &sA[s][(row0 + 64) * STR + cq * 4];
        uint32_t* pb0 = &sB[s][row0 * STR + cq * 4];
        uint32_t* pb1 = &sB[s][(row0 + 64) * STR + cq * 4];
        pa0[0] = f2tf32(a0.x); pa0[1] = f2tf32(a0.y); pa0[2] = f2tf32(a0.z); pa0[3] = f2tf32(a0.w);
        pa1[0] = f2tf32(a1.x); pa1[1] = f2tf32(a1.y); pa1[2] = f2tf32(a1.z); pa1[3] = f2tf32(a1.w);
        pb0[0] = f2tf32(b0.x); pb0[1] = f2tf32(b0.y); pb0[2] = f2tf32(b0.z); pb0[3] = f2tf32(b0.w);
        pb1[0] = f2tf32(b1.x); pb1[1] = f2tf32(b1.y); pb1[2] = f2tf32(b1.z); pb1[3] = f2tf32(b1.w);
    };

    store_stage(0, ra0, ra1, rb0, rb1);
    __syncthreads();

    for (int c = 0; c < CHUNKS; ++c) {
        const int s = c & 1;
        // issue next chunk's global loads early (latency hidden under compute)
        if (c + 1 < CHUNKS) {
            const int off = (c + 1) * (BK / 4);      // float4 offset along K
            ra0 = gA0[off]; ra1 = gA1[off]; rb0 = gB0[off]; rb1 = gB1[off];
        }

        // compute on stage s
        const uint32_t* As = sA[s];
        const uint32_t* Bs = sB[s];
#pragma unroll
        for (int ks = 0; ks < BK / 8; ++ks) {
            const int k0c = ks * 8 + t;
            uint32_t a[4][4], bfr[4][2];
#pragma unroll
            for (int i = 0; i < 4; ++i) {
                int r0 = wm + 16 * i + g, r1 = r0 + 8;
                a[i][0] = As[r0 * STR + k0c];
                a[i][1] = As[r1 * STR + k0c];
                a[i][2] = As[r0 * STR + k0c + 4];
                a[i][3] = As[r1 * STR + k0c + 4];
            }
#pragma unroll
            for (int j = 0; j < 4; ++j) {
                int n = wn + 8 * j + g;
                bfr[j][0] = Bs[n * STR + k0c];
                bfr[j][1] = Bs[n * STR + k0c + 4];
            }
#pragma unroll
            for (int i = 0; i < 4; ++i)
#pragma unroll
                for (int j = 0; j < 4; ++j)
                    mma_tf32(acc[i][j], a[i], bfr[j]);
        }

        __syncthreads();                     // stage (1-s) reads (iter c-1) done everywhere
        if (c + 1 < CHUNKS) {
            store_stage(1 - s, ra0, ra1, rb0, rb1);
            __syncthreads();                 // stores visible before next compute
        }
    }

    // ---- epilogue: register-resident max over 16-shot classes ----
    if (tid < BN) trs[tid] = g_trsq[b * COLS + c0 + tid];
    else          tes[tid - BN] = g_tesq[b * PM + m0 + (tid - BN)];
    __syncthreads();

    float trq[4][2];
#pragma unroll
    for (int j = 0; j < 4; ++j) {
        trq[j][0] = trs[wn + 8 * j + 2 * t];
        trq[j][1] = trs[wn + 8 * j + 2 * t + 1];
    }

#pragma unroll
    for (int i = 0; i < 4; ++i) {
        int r0 = wm + 16 * i + g, r1 = r0 + 8;
        float te0 = tes[r0], te1 = tes[r1];
#pragma unroll
        for (int u = 0; u < 2; ++u) {         // class index within warp (16 cols each)
            float m0v = -3.4e38f, m1v = -3.4e38f;
#pragma unroll
            for (int jj = 0; jj < 2; ++jj) {
                int j = 2 * u + jj;
                m0v = fmaxf(m0v, fmaxf(2.f * acc[i][j][0] - trq[j][0],
                                       2.f * acc[i][j][1] - trq[j][1]));
                m1v = fmaxf(m1v, fmaxf(2.f * acc[i][j][2] - trq[j][0],
                                       2.f * acc[i][j][3] - trq[j][1]));
            }
            // reduce across the 4 lanes of the t-quad (same g)
            m0v = fmaxf(m0v, __shfl_xor_sync(0xffffffffu, m0v, 1));
            m0v = fmaxf(m0v, __shfl_xor_sync(0xffffffffu, m0v, 2));
            m1v = fmaxf(m1v, __shfl_xor_sync(0xffffffffu, m1v, 1));
            m1v = fmaxf(m1v, __shfl_xor_sync(0xffffffffu, m1v, 2));
            if (t == 0) {
                int cls = blockIdx.x * (BN / PN) + (wn >> 4) + u;
                out[((size_t)b * PM + m0 + r0) * PK + cls] = m0v - te0;
                out[((size_t)b * PM + m0 + r1) * PK + cls] = m1v - te1;
            }
        }
    }
}

// ---------------------------------------------------------------------------
extern "C" void kernel_launch(void* const* d_in, const int* in_sizes, int n_in,
                              void* d_out, int out_size)
{
    const float* train = (const float*)d_in[0];
    const float* test  = (const float*)d_in[1];
    if (in_sizes[0] == PB * PM * PD && in_sizes[1] == PB * COLS * PD) {
        train = (const float*)d_in[1];
        test  = (const float*)d_in[0];
    }
    float* out = (float*)d_out;

    sumsq_kernel<<<(PB * COLS) / 8, 256>>>(train, PB * COLS, 0);
    sumsq_kernel<<<(PB * PM) / 8, 256>>>(test,  PB * PM, 1);

    dim3 grid(COLS / BN, PM / BM, PB);   // (8, 4, 64)
    nearest_mma<<<grid, NTHREADS>>>(train, test, out);
}

// round 9
// speedup vs baseline: 3.3627x; 1.0434x over previous
#include <cuda_runtime.h>
#include <cstdint>
#include <cstddef>

// ---------------- problem constants ----------------
#define PB 64
#define PK 64
#define PN 16
#define PM 512
#define PD 512
#define COLS (PK * PN)        // 1024 train rows per batch

// ---------------- GEMM tiling ----------------
#define BM 128                // test rows per CTA
#define BN 128                // train rows per CTA
#define BK 16                 // K per chunk
#define CHUNKS (PD / BK)      // 32
#define NTHREADS 256
#define STR 20                // smem row stride in elements (padding: conflict-free)

__device__ __forceinline__ uint32_t f2tf32(float f) {
    uint32_t u;
    asm("cvt.rna.tf32.f32 %0, %1;" : "=r"(u) : "f"(f));
    return u;
}
__device__ __forceinline__ void mma_tf32(float* c, const uint32_t* a, const uint32_t* b) {
    asm volatile(
        "mma.sync.aligned.m16n8k8.row.col.f32.tf32.tf32.f32 "
        "{%0,%1,%2,%3}, {%4,%5,%6,%7}, {%8,%9}, {%0,%1,%2,%3};"
        : "+f"(c[0]), "+f"(c[1]), "+f"(c[2]), "+f"(c[3])
        : "r"(a[0]), "r"(a[1]), "r"(a[2]), "r"(a[3]), "r"(b[0]), "r"(b[1]));
}
__device__ __forceinline__ float dot4(const float4& v) {
    return v.x * v.x + v.y * v.y + v.z * v.z + v.w * v.w;
}

// ---------------------------------------------------------------------------
// Fused kernel: tf32 mma.sync GEMM + on-the-fly squared norms +
// register-resident max-over-shots epilogue.
// CTA: 128(m) x 128(n) x 512(k); 8 warps (2m x 4n), warp tile 64x32.
// Register-staged double buffer (NO cp.async). Layout identical to the
// known-good R6 kernel (STR=20, unpermuted, scalar fragment LDS).
// ---------------------------------------------------------------------------
__global__ __launch_bounds__(NTHREADS, 2)
void nearest_mma(const float* __restrict__ train, const float* __restrict__ test,
                 float* __restrict__ out)
{
    __shared__ uint32_t sA[2][BM * STR];
    __shared__ uint32_t sB[2][BN * STR];
    __shared__ float trs[BN], tes[BM];
    __shared__ float trsP[BN * 4], tesP[BM * 4];

    const int tid  = threadIdx.x;
    const int wid  = tid >> 5;
    const int lane = tid & 31;
    const int g = lane >> 2;              // 0..7
    const int t = lane & 3;               // 0..3
    const int wm = (wid & 1) * 64;        // warp m offset
    const int wn = (wid >> 1) * 32;       // warp n offset (= 2 classes)

    const int b  = blockIdx.z;
    const int m0 = blockIdx.y * BM;
    const int c0 = blockIdx.x * BN;

    const float* test_b  = test  + ((size_t)b * PM   + m0) * PD;
    const float* train_b = train + ((size_t)b * COLS + c0) * PD;

    // per-thread staging coordinates: 512 float4 per operand tile / 256 threads
    const int row0 = tid >> 2;                 // 0..63
    const int cq   = tid & 3;                  // float4 slot within 16 floats
    const float4* gA0 = reinterpret_cast<const float4*>(test_b  + (size_t)row0        * PD) + cq;
    const float4* gA1 = reinterpret_cast<const float4*>(test_b  + (size_t)(row0 + 64) * PD) + cq;
    const float4* gB0 = reinterpret_cast<const float4*>(train_b + (size_t)row0        * PD) + cq;
    const float4* gB1 = reinterpret_cast<const float4*>(train_b + (size_t)(row0 + 64) * PD) + cq;

    float acc[4][4][4];
#pragma unroll
    for (int i = 0; i < 4; ++i)
#pragma unroll
        for (int j = 0; j < 4; ++j)
#pragma unroll
            for (int r = 0; r < 4; ++r) acc[i][j][r] = 0.f;

    float aq0 = 0.f, aq1 = 0.f, bq0 = 0.f, bq1 = 0.f;   // fused sumsq partials

    float4 ra0, ra1, rb0, rb1;
    // load chunk 0
    ra0 = gA0[0]; ra1 = gA1[0]; rb0 = gB0[0]; rb1 = gB1[0];
    aq0 += dot4(ra0); aq1 += dot4(ra1); bq0 += dot4(rb0); bq1 += dot4(rb1);

    // store helper (tf32-convert at store time) — unpermuted, as in R6
    auto store_stage = [&](int s, const float4& a0, const float4& a1,
                           const float4& b0, const float4& b1) {
        uint32_t* pa0 = &sA[s][row0 * STR + cq * 4];
        uint32_t* pa1 = &sA[s][(row0 + 64) * STR + cq * 4];
        uint32_t* pb0 = &sB[s][row0 * STR + cq * 4];
        uint32_t* pb1 = &sB[s][(row0 + 64) * STR + cq * 4];
        pa0[0] = f2tf32(a0.x); pa0[1] = f2tf32(a0.y); pa0[2] = f2tf32(a0.z); pa0[3] = f2tf32(a0.w);
        pa1[0] = f2tf32(a1.x); pa1[1] = f2tf32(a1.y); pa1[2] = f2tf32(a1.z); pa1[3] = f2tf32(a1.w);
        pb0[0] = f2tf32(b0.x); pb0[1] = f2tf32(b0.y); pb0[2] = f2tf32(b0.z); pb0[3] = f2tf32(b0.w);
        pb1[0] = f2tf32(b1.x); pb1[1] = f2tf32(b1.y); pb1[2] = f2tf32(b1.z); pb1[3] = f2tf32(b1.w);
    };

    store_stage(0, ra0, ra1, rb0, rb1);
    __syncthreads();

    for (int c = 0; c < CHUNKS; ++c) {
        const int s = c & 1;
        // issue next chunk's global loads early (latency hidden under compute)
        if (c + 1 < CHUNKS) {
            const int off = (c + 1) * (BK / 4);      // float4 offset along K
            ra0 = gA0[off]; ra1 = gA1[off]; rb0 = gB0[off]; rb1 = gB1[off];
            aq0 += dot4(ra0); aq1 += dot4(ra1); bq0 += dot4(rb0); bq1 += dot4(rb1);
        }

        // compute on stage s
        const uint32_t* As = sA[s];
        const uint32_t* Bs = sB[s];
#pragma unroll
        for (int ks = 0; ks < BK / 8; ++ks) {
            const int k0c = ks * 8 + t;
            uint32_t a[4][4], bfr[4][2];
#pragma unroll
            for (int i = 0; i < 4; ++i) {
                int r0 = wm + 16 * i + g, r1 = r0 + 8;
                a[i][0] = As[r0 * STR + k0c];
                a[i][1] = As[r1 * STR + k0c];
                a[i][2] = As[r0 * STR + k0c + 4];
                a[i][3] = As[r1 * STR + k0c + 4];
            }
#pragma unroll
            for (int j = 0; j < 4; ++j) {
                int n = wn + 8 * j + g;
                bfr[j][0] = Bs[n * STR + k0c];
                bfr[j][1] = Bs[n * STR + k0c + 4];
            }
#pragma unroll
            for (int i = 0; i < 4; ++i)
#pragma unroll
                for (int j = 0; j < 4; ++j)
                    mma_tf32(acc[i][j], a[i], bfr[j]);
        }

        __syncthreads();                     // stage (1-s) reads (iter c-1) done everywhere
        if (c + 1 < CHUNKS) {
            store_stage(1 - s, ra0, ra1, rb0, rb1);
            __syncthreads();                 // stores visible before next compute
        }
    }

    // ---- reduce fused norms: 4 partials (cq) per row ----
    tesP[row0 * 4 + cq] = aq0;  tesP[(row0 + 64) * 4 + cq] = aq1;
    trsP[row0 * 4 + cq] = bq0;  trsP[(row0 + 64) * 4 + cq] = bq1;
    __syncthreads();
    if (tid < BM) {
        tes[tid] = tesP[tid * 4] + tesP[tid * 4 + 1] + tesP[tid * 4 + 2] + tesP[tid * 4 + 3];
    } else {
        int r = tid - BM;
        trs[r] = trsP[r * 4] + trsP[r * 4 + 1] + trsP[r * 4 + 2] + trsP[r * 4 + 3];
    }
    __syncthreads();

    // ---- epilogue: register-resident max over 16-shot classes ----
    float trq[4][2];
#pragma unroll
    for (int j = 0; j < 4; ++j) {
        trq[j][0] = trs[wn + 8 * j + 2 * t];
        trq[j][1] = trs[wn + 8 * j + 2 * t + 1];
    }

#pragma unroll
    for (int i = 0; i < 4; ++i) {
        int r0 = wm + 16 * i + g, r1 = r0 + 8;
        float te0 = tes[r0], te1 = tes[r1];
#pragma unroll
        for (int u = 0; u < 2; ++u) {         // class index within warp (16 cols each)
            float m0v = -3.4e38f, m1v = -3.4e38f;
#pragma unroll
            for (int jj = 0; jj < 2; ++jj) {
                int j = 2 * u + jj;
                m0v = fmaxf(m0v, fmaxf(2.f * acc[i][j][0] - trq[j][0],
                                       2.f * acc[i][j][1] - trq[j][1]));
                m1v = fmaxf(m1v, fmaxf(2.f * acc[i][j][2] - trq[j][0],
                                       2.f * acc[i][j][3] - trq[j][1]));
            }
            // reduce across the 4 lanes of the t-quad (same g)
            m0v = fmaxf(m0v, __shfl_xor_sync(0xffffffffu, m0v, 1));
            m0v = fmaxf(m0v, __shfl_xor_sync(0xffffffffu, m0v, 2));
            m1v = fmaxf(m1v, __shfl_xor_sync(0xffffffffu, m1v, 1));
            m1v = fmaxf(m1v, __shfl_xor_sync(0xffffffffu, m1v, 2));
            if (t == 0) {
                int cls = blockIdx.x * (BN / PN) + (wn >> 4) + u;
                out[((size_t)b * PM + m0 + r0) * PK + cls] = m0v - te0;
                out[((size_t)b * PM + m0 + r1) * PK + cls] = m1v - te1;
            }
        }
    }
}

// ---------------------------------------------------------------------------
extern "C" void kernel_launch(void* const* d_in, const int* in_sizes, int n_in,
                              void* d_out, int out_size)
{
    const float* train = (const float*)d_in[0];
    const float* test  = (const float*)d_in[1];
    if (in_sizes[0] == PB * PM * PD && in_sizes[1] == PB * COLS * PD) {
        train = (const float*)d_in[1];
        test  = (const float*)d_in[0];
    }
    float* out = (float*)d_out;

    dim3 grid(COLS / BN, PM / BM, PB);   // (8, 4, 64)
    nearest_mma<<<grid, NTHREADS>>>(train, test, out);
}